// round 12
// baseline (speedup 1.0000x reference)
#include <cuda_runtime.h>
#include <cuda_bf16.h>
#include <cstdint>

// MMDLayer via mma.sync bf16 (HMMA), 2-way bf16 split (hh+hl+lh).
// out[t,s] = (1 - (||x_t||^2 + ||C_k||^2 - 2 x_t.C_k)/128)^3,  k = 511+t-s
// C[k] = init[511-k] (k<512) else x[k-512];  A row t == C[512+t].
// Kernel 1 (prep): split C rows into QUARTER-MAJOR bf16 scratch: plane q holds
//   k-cols [32q,32q+32) of each row as 128B (4 hi + 4 lo 16B chunks, XOR-swizzled
//   chunk c -> c^(row&7)) + fp32 norms. PDL launch_dependents at end.
// Kernel 2 (main): PDL wait; per k-quarter stage s: bulk-DMA A(8KB)+B(8KB) on
//   mbar[s]; compute k-steps {2s,2s+1} as soon as stage lands (DMA/HMMA overlap).
//   64x64 tile/CTA, 8 warps, 32x16 warp tiles.

#define T_LEN 2048
#define S_LEN 512
#define DIM   128
#define NROWS 2560
#define NROWS_PAD 2624
#define BT    64
#define BK    64
#define NKT   9
#define NTHR  256

#define PLANE (NROWS_PAD * 128)       // bytes per k-quarter plane

// ---- smem layout (bytes): 4 stages x (A 8KB + B 8KB) ----
#define STG(s)   ((s) * 16384)
#define OFF_B_ST 8192                 // B offset within a stage
#define OFF_NA   65536                // 64 A norms (256B)
#define OFF_NB   65792                // 64 B norms (256B)
#define OFF_MB   66048                // 4 mbarriers
#define SMEM_TOTAL 66112

// ---- global scratch (device globals: allocation-free) ----
__device__ __align__(256) unsigned char g_c[4 * PLANE];
__device__ __align__(256) float         g_nrm[NROWS_PAD];

__device__ __forceinline__ uint32_t smem_u32(const void* p) {
    uint32_t a;
    asm("{ .reg .u64 t; cvta.to.shared.u64 t, %1; cvt.u32.u64 %0, t; }" : "=r"(a) : "l"(p));
    return a;
}
__device__ __forceinline__ void ldsm4(uint32_t r[4], uint32_t addr) {
    asm volatile("ldmatrix.sync.aligned.m8n8.x4.shared.b16 {%0,%1,%2,%3}, [%4];"
                 : "=r"(r[0]), "=r"(r[1]), "=r"(r[2]), "=r"(r[3]) : "r"(addr));
}
__device__ __forceinline__ void mma16816(float c[4], const uint32_t a[4],
                                         uint32_t b0, uint32_t b1) {
    asm volatile(
        "mma.sync.aligned.m16n8k16.row.col.f32.bf16.bf16.f32 "
        "{%0,%1,%2,%3}, {%4,%5,%6,%7}, {%8,%9}, {%0,%1,%2,%3};"
        : "+f"(c[0]), "+f"(c[1]), "+f"(c[2]), "+f"(c[3])
        : "r"(a[0]), "r"(a[1]), "r"(a[2]), "r"(a[3]), "r"(b0), "r"(b1));
}
__device__ __forceinline__ void bulk_g2s(uint32_t dst, const void* src,
                                         uint32_t bytes, uint32_t mbar) {
    asm volatile(
        "cp.async.bulk.shared::cluster.global.mbarrier::complete_tx::bytes "
        "[%0], [%1], %2, [%3];"
        :: "r"(dst), "l"(src), "r"(bytes), "r"(mbar) : "memory");
}
__device__ __forceinline__ unsigned short us(__nv_bfloat16 h) {
    return __bfloat16_as_ushort(h);
}

#define MBAR_WAIT_P0(mbar) do {                                                  \
    asm volatile(                                                                \
        "{\n\t.reg .pred P1;\n\t"                                                \
        "WAIT_LOOP_%=:\n\t"                                                      \
        "mbarrier.try_wait.parity.acquire.cta.shared::cta.b64 P1, [%0], 0, 0x989680;\n\t" \
        "@P1 bra.uni WAIT_DONE_%=;\n\t"                                          \
        "bra.uni WAIT_LOOP_%=;\n\t"                                              \
        "WAIT_DONE_%=:\n\t}"                                                     \
        :: "r"(mbar) : "memory");                                                \
} while (0)

// ---- Kernel 1: split rows into quarter-major hi/lo bf16 + norms ----
__global__ __launch_bounds__(NTHR)
void prep_kernel(const float* __restrict__ x, const float* __restrict__ init)
{
    const int wid  = threadIdx.x >> 5;
    const int lane = threadIdx.x & 31;
    const int row  = blockIdx.x * 8 + wid;          // grid = 328 -> rows 0..2623
    const int rs   = row < NROWS - 1 ? row : NROWS - 1;

    const float* src = (rs < S_LEN) ? init + (size_t)(S_LEN - 1 - rs) * DIM
                                    : x    + (size_t)(rs - S_LEN) * DIM;
    const float4 v = reinterpret_cast<const float4*>(src)[lane];

    __nv_bfloat16 h0 = __float2bfloat16_rn(v.x);
    __nv_bfloat16 h1 = __float2bfloat16_rn(v.y);
    __nv_bfloat16 h2 = __float2bfloat16_rn(v.z);
    __nv_bfloat16 h3 = __float2bfloat16_rn(v.w);
    __nv_bfloat16 l0 = __float2bfloat16_rn(v.x - __bfloat162float(h0));
    __nv_bfloat16 l1 = __float2bfloat16_rn(v.y - __bfloat162float(h1));
    __nv_bfloat16 l2 = __float2bfloat16_rn(v.z - __bfloat162float(h2));
    __nv_bfloat16 l3 = __float2bfloat16_rn(v.w - __bfloat162float(h3));

    uint2 H = make_uint2((uint32_t)us(h0) | ((uint32_t)us(h1) << 16),
                         (uint32_t)us(h2) | ((uint32_t)us(h3) << 16));
    uint2 L = make_uint2((uint32_t)us(l0) | ((uint32_t)us(l1) << 16),
                         (uint32_t)us(l2) | ((uint32_t)us(l3) << 16));

    const int q    = lane >> 3;                     // k-quarter
    const int chi  = (lane & 7) >> 1;               // hi chunk 0..3
    const int half = lane & 1;                      // 8B half within chunk
    const int rx   = row & 7;
    unsigned char* base = g_c + (size_t)q * PLANE + (size_t)row * 128;
    *reinterpret_cast<uint2*>(base + (((chi)     ^ rx) << 4) + half * 8) = H;
    *reinterpret_cast<uint2*>(base + (((chi + 4) ^ rx) << 4) + half * 8) = L;

    float p = v.x * v.x + v.y * v.y + v.z * v.z + v.w * v.w;
    #pragma unroll
    for (int o = 16; o; o >>= 1) p += __shfl_xor_sync(0xFFFFFFFFu, p, o);
    if (lane == 0) g_nrm[row] = p;

    asm volatile("griddepcontrol.launch_dependents;" ::: "memory");
}

// ---- Kernel 2: banded HMMA GEMM, k-quarter pipelined bulk-DMA ----
__global__ __launch_bounds__(NTHR, 2)
void mmd_mma_kernel(float* __restrict__ out)
{
    extern __shared__ char sm[];
    const uint32_t smb = smem_u32(sm);
    const int tid  = threadIdx.x;
    const int wid  = tid >> 5;
    const int lane = tid & 31;
    const int bx = blockIdx.x;
    const int t0 = blockIdx.y * BT;
    const int k0 = t0 + BK * bx;

    if (tid == 0) {
        #pragma unroll
        for (int s = 0; s < 4; s++)
            asm volatile("mbarrier.init.shared.b64 [%0], 1;"
                         :: "r"(smb + OFF_MB + 8 * s) : "memory");
    }
    __syncthreads();

    if (tid == 0) {
        asm volatile("griddepcontrol.wait;" ::: "memory");
        const unsigned char* gc = g_c;
        const char* gnr = reinterpret_cast<const char*>(g_nrm);
        #pragma unroll
        for (int s = 0; s < 4; s++) {
            const uint32_t mb = smb + OFF_MB + 8 * s;
            const uint32_t tx = (s == 0) ? 16896u : 16384u;
            asm volatile("mbarrier.arrive.expect_tx.shared.b64 _, [%0], %1;"
                         :: "r"(mb), "r"(tx) : "memory");
            bulk_g2s(smb + STG(s),            gc + (size_t)s * PLANE + (size_t)(S_LEN + t0) * 128, 8192, mb);
            bulk_g2s(smb + STG(s) + OFF_B_ST, gc + (size_t)s * PLANE + (size_t)k0 * 128,           8192, mb);
            if (s == 0) {
                bulk_g2s(smb + OFF_NA, gnr + (size_t)(S_LEN + t0) * 4, 256, mb);
                bulk_g2s(smb + OFF_NB, gnr + (size_t)k0 * 4,           256, mb);
            }
        }
    }

    // ---- Warp tiling: 2 warps M (32 rows each) x 4 warps N (16 cols each) ----
    const int wm = wid & 1;
    const int wn = wid >> 1;

    const int arow = wm * 32 + (lane & 7) + ((lane >> 3) & 1) * 8;
    const int qa0  = lane >> 4;              // 16B chunk within k-step (col 0 / col 8)
    const int rxa  = arow & 7;
    const uint32_t aBase0 = smb + (uint32_t)(arow * 128);
    const uint32_t aBase1 = aBase0 + 16 * 128;
    const int rxa1 = (arow + 16) & 7;        // == rxa (16 ≡ 0 mod 8)

    const int brow = wn * 16 + (lane & 7) + (lane >> 4) * 8;
    const int qb0  = (lane >> 3) & 1;
    const int rxb  = brow & 7;
    const uint32_t bBase = smb + OFF_B_ST + (uint32_t)(brow * 128);

    float acc[2][2][4];
    #pragma unroll
    for (int i = 0; i < 2; i++)
        #pragma unroll
        for (int j = 0; j < 2; j++)
            #pragma unroll
            for (int q = 0; q < 4; q++)
                acc[i][j][q] = 0.f;

    // ---- Main loop: 4 stages x 2 k-steps; hh + hl + lh per k-step ----
    #pragma unroll
    for (int s = 0; s < 4; s++) {
        MBAR_WAIT_P0(smb + OFF_MB + 8 * s);
        const uint32_t sb = (uint32_t)STG(s);
        #pragma unroll
        for (int kk = 0; kk < 2; kk++) {
            const int ca = 2 * kk + qa0;         // hi chunk id (lo = +4)
            const int cb = 2 * kk + qb0;
            const uint32_t qaH = (uint32_t)(((ca)     ^ rxa) << 4);
            const uint32_t qaL = (uint32_t)(((ca + 4) ^ rxa) << 4);
            const uint32_t qbH = (uint32_t)(((cb)     ^ rxb) << 4);
            const uint32_t qbL = (uint32_t)(((cb + 4) ^ rxb) << 4);
            uint32_t ah0[4], ah1[4], al0[4], al1[4], bh[4], bl[4];
            ldsm4(ah0, sb + aBase0 + qaH);
            ldsm4(ah1, sb + aBase1 + (uint32_t)(((ca)     ^ rxa1) << 4));
            ldsm4(al0, sb + aBase0 + qaL);
            ldsm4(al1, sb + aBase1 + (uint32_t)(((ca + 4) ^ rxa1) << 4));
            ldsm4(bh,  sb + bBase + qbH);
            ldsm4(bl,  sb + bBase + qbL);

            mma16816(acc[0][0], ah0, bh[0], bh[1]);   // hh
            mma16816(acc[0][1], ah0, bh[2], bh[3]);
            mma16816(acc[1][0], ah1, bh[0], bh[1]);
            mma16816(acc[1][1], ah1, bh[2], bh[3]);
            mma16816(acc[0][0], ah0, bl[0], bl[1]);   // hl
            mma16816(acc[0][1], ah0, bl[2], bl[3]);
            mma16816(acc[1][0], ah1, bl[0], bl[1]);
            mma16816(acc[1][1], ah1, bl[2], bl[3]);
            mma16816(acc[0][0], al0, bh[0], bh[1]);   // lh
            mma16816(acc[0][1], al0, bh[2], bh[3]);
            mma16816(acc[1][0], al1, bh[0], bh[1]);
            mma16816(acc[1][1], al1, bh[2], bh[3]);
        }
    }

    // ---- Norms from smem ----
    const float* sNA = (const float*)(sm + OFF_NA);
    const float* sNB = (const float*)(sm + OFF_NB);
    const int nbase = wn * 16 + 2 * (lane & 3);
    float nb[2][2];
    #pragma unroll
    for (int nt = 0; nt < 2; nt++) {
        nb[nt][0] = sNB[nbase + nt * 8];
        nb[nt][1] = sNB[nbase + nt * 8 + 1];
    }

    // ---- Epilogue: d2 = nA + nB - 2*dot; out[t, 511+t-k] = (1 - d2/128)^3 ----
    #pragma unroll
    for (int mt = 0; mt < 2; mt++) {
        const int m  = wm * 32 + mt * 16 + (lane >> 2);
        const float na0 = sNA[m];
        const float na1 = sNA[m + 8];
        const int ta = t0 + m;
        const int tb = ta + 8;
        #pragma unroll
        for (int nt = 0; nt < 2; nt++) {
            const int n  = nbase + nt * 8;
            const int k  = k0 + n;
            const float* a4 = acc[mt][nt];

            const int sa = 511 + ta - k;
            const int sb2 = 511 + tb - k;
            float d2, u;
            if (sa >= 0 && sa < S_LEN) {
                d2 = na0 + nb[nt][0] - 2.0f * a4[0];
                u  = 1.0f - d2 * (1.0f / 128.0f);
                out[(size_t)ta * S_LEN + sa] = u * u * u;
            }
            if ((unsigned)(sa - 1) < S_LEN) {
                d2 = na0 + nb[nt][1] - 2.0f * a4[1];
                u  = 1.0f - d2 * (1.0f / 128.0f);
                out[(size_t)ta * S_LEN + sa - 1] = u * u * u;
            }
            if (sb2 >= 0 && sb2 < S_LEN) {
                d2 = na1 + nb[nt][0] - 2.0f * a4[2];
                u  = 1.0f - d2 * (1.0f / 128.0f);
                out[(size_t)tb * S_LEN + sb2] = u * u * u;
            }
            if ((unsigned)(sb2 - 1) < S_LEN) {
                d2 = na1 + nb[nt][1] - 2.0f * a4[3];
                u  = 1.0f - d2 * (1.0f / 128.0f);
                out[(size_t)tb * S_LEN + sb2 - 1] = u * u * u;
            }
        }
    }
}

extern "C" void kernel_launch(void* const* d_in, const int* in_sizes, int n_in,
                              void* d_out, int out_size)
{
    const float* x    = (const float*)d_in[0];   // (1, 2048, 1, 128) fp32
    const float* init = (const float*)d_in[1];   // (512, 128) fp32
    float* out = (float*)d_out;                  // (1, 2048, 512) fp32

    cudaFuncSetAttribute(mmd_mma_kernel,
                         cudaFuncAttributeMaxDynamicSharedMemorySize, SMEM_TOTAL);

    prep_kernel<<<NROWS_PAD / 8, NTHR>>>(x, init);   // 328 CTAs

    cudaLaunchConfig_t cfg = {};
    cfg.gridDim  = dim3(NKT, T_LEN / BT, 1);         // (9, 32) = 288 CTAs
    cfg.blockDim = dim3(NTHR, 1, 1);
    cfg.dynamicSmemBytes = SMEM_TOTAL;
    cudaLaunchAttribute attr[1];
    attr[0].id = cudaLaunchAttributeProgrammaticStreamSerialization;
    attr[0].val.programmaticStreamSerializationAllowed = 1;
    cfg.attrs = attr;
    cfg.numAttrs = 1;
    cudaLaunchKernelEx(&cfg, mmd_mma_kernel, out);
}